// round 11
// baseline (speedup 1.0000x reference)
#include <cuda_runtime.h>
#include <cuda_bf16.h>
#include <cuda_fp16.h>

#define N_NODES 100000
#define N_EDGES 1600000
#define C       128
#define NCLS    16
#define DCAT    512   // 128 + 3*128
#define SB      1024
#define NB      ((N_NODES + SB - 1) / SB)   // 98 scan blocks

// ---- scratch (device globals: no allocation allowed) ----
__device__ __half g_tmp16[(size_t)N_NODES * C];  // x_prev @ W, fp16 (25.6 MB)
__device__ float  g_dis[N_NODES];                // rsqrt(degree)
__device__ int    g_cnt[N_NODES];                // in-degree counts
__device__ int    g_rowstart[N_NODES + 1];       // CSR row offsets
__device__ int    g_cursor[N_NODES];             // fill cursors
__device__ int    g_bsum[NB];                    // scan block sums
__device__ int    g_boff[NB];                    // scan block offsets
__device__ int2   g_csr[N_EDGES];                // CSR: {src, dis[src] bits}
__device__ __nv_bfloat16 g_Wt_hi[3][C * C];      // W^T [n][k] hi, per layer
__device__ __nv_bfloat16 g_Wt_lo[3][C * C];      // W^T [n][k] lo, per layer

// ---------------------------------------------------------------------------
__global__ void k_init(const float* __restrict__ x, float* __restrict__ h) {
    int t = blockIdx.x * blockDim.x + threadIdx.x;
    if (t >= N_NODES * 32) return;
    int node = t >> 5;
    int lane = t & 31;
    float4 v = ((const float4*)(x + (size_t)node * C))[lane];
    ((float4*)(h + (size_t)node * DCAT))[lane] = v;
    if (lane == 0) g_cnt[node] = 0;
}

__global__ void k_wconv(const float* __restrict__ W0,
                        const float* __restrict__ W1,
                        const float* __restrict__ W2) {
    int idx = blockIdx.x * blockDim.x + threadIdx.x;
    if (idx >= 3 * C * C) return;
    int l = idx / (C * C);
    int r = idx - l * (C * C);
    const float* W = (l == 0) ? W0 : (l == 1) ? W1 : W2;
    int k = r >> 7;
    int n = r & 127;
    float v = W[r];
    __nv_bfloat16 hi = __float2bfloat16_rn(v);
    float lo = v - __bfloat162float(hi);
    g_Wt_hi[l][n * C + k] = hi;
    g_Wt_lo[l][n * C + k] = __float2bfloat16_rn(lo);
}

__global__ void k_deg(const int* __restrict__ ei) {
    int e = blockIdx.x * blockDim.x + threadIdx.x;
    if (e >= N_EDGES) return;
    atomicAdd(&g_cnt[ei[N_EDGES + e]], 1);
}

// ---------------------------------------------------------------------------
// Multi-block scan
// ---------------------------------------------------------------------------
__global__ void k_scanA() {
    int i = blockIdx.x * SB + threadIdx.x;
    int lane = threadIdx.x & 31, wid = threadIdx.x >> 5;
    int v = (i < N_NODES) ? g_cnt[i] : 0;
    int s = v;
#pragma unroll
    for (int o = 1; o < 32; o <<= 1) {
        int t = __shfl_up_sync(0xffffffffu, s, o);
        if (lane >= o) s += t;
    }
    __shared__ int wsum[32];
    if (lane == 31) wsum[wid] = s;
    __syncthreads();
    if (wid == 0) {
        int t = wsum[lane];
#pragma unroll
        for (int o = 1; o < 32; o <<= 1) {
            int u = __shfl_up_sync(0xffffffffu, t, o);
            if (lane >= o) t += u;
        }
        wsum[lane] = t;
    }
    __syncthreads();
    int incl = s + (wid > 0 ? wsum[wid - 1] : 0);
    if (i < N_NODES) g_rowstart[i] = incl - v;
    if (threadIdx.x == SB - 1) g_bsum[blockIdx.x] = incl;
}

__global__ void k_scanB() {
    int tid = threadIdx.x;
    int lane = tid & 31, wid = tid >> 5;
    int v = (tid < NB) ? g_bsum[tid] : 0;
    int s = v;
#pragma unroll
    for (int o = 1; o < 32; o <<= 1) {
        int t = __shfl_up_sync(0xffffffffu, s, o);
        if (lane >= o) s += t;
    }
    __shared__ int wsum[4];
    if (lane == 31) wsum[wid] = s;
    __syncthreads();
    int woff = 0;
    for (int w = 0; w < wid; ++w) woff += wsum[w];
    int incl = s + woff;
    if (tid < NB) g_boff[tid] = incl - v;
    if (tid == NB - 1) g_rowstart[N_NODES] = incl;
}

__global__ void k_scanC() {
    int i = blockIdx.x * blockDim.x + threadIdx.x;
    if (i >= N_NODES) return;
    int e = g_rowstart[i] + g_boff[i >> 10];
    g_rowstart[i] = e;
    g_cursor[i]   = e;
    g_dis[i]      = rsqrtf((float)(g_cnt[i] + 1));
}

__global__ void k_fill(const int* __restrict__ ei) {
    int e = blockIdx.x * blockDim.x + threadIdx.x;
    if (e >= N_EDGES) return;
    int s = ei[e];
    int d = ei[N_EDGES + e];
    int pos = atomicAdd(&g_cursor[d], 1);
    g_csr[pos] = make_int2(s, __float_as_int(g_dis[s]));
}

// ---------------------------------------------------------------------------
// GEMM (tensor-core, bf16 split): g_tmp16 = fp16(in @ W)
// acc = hi@Whi + lo@Whi + hi@Wlo  (fp32 accumulate)
// ---------------------------------------------------------------------------
#define APAD 40
__device__ __forceinline__ void mma_bf16(float c[4], const unsigned a[4],
                                         const unsigned b[2]) {
    asm volatile(
        "mma.sync.aligned.m16n8k16.row.col.f32.bf16.bf16.f32 "
        "{%0,%1,%2,%3}, {%4,%5,%6,%7}, {%8,%9}, {%0,%1,%2,%3};\n"
        : "+f"(c[0]), "+f"(c[1]), "+f"(c[2]), "+f"(c[3])
        : "r"(a[0]), "r"(a[1]), "r"(a[2]), "r"(a[3]), "r"(b[0]), "r"(b[1]));
}

__global__ void __launch_bounds__(256)
k_gemm_tc(const float* __restrict__ in, int layer) {
    __shared__ __nv_bfloat16 a_hi[128][APAD];
    __shared__ __nv_bfloat16 a_lo[128][APAD];
    __shared__ __nv_bfloat16 b_hi[128][APAD];
    __shared__ __nv_bfloat16 b_lo[128][APAD];

    const __nv_bfloat16* Whi = g_Wt_hi[layer];
    const __nv_bfloat16* Wlo = g_Wt_lo[layer];

    int tid  = threadIdx.x;
    int lane = tid & 31;
    int wid  = tid >> 5;
    int wm   = wid & 1;
    int wn   = wid >> 1;
    int row0 = blockIdx.x * 128;

    int arow = tid >> 1;
    int akb  = (tid & 1) * 16;
    int grow = row0 + arow;
    if (grow >= N_NODES) grow = N_NODES - 1;
    const float* aptr = in + (size_t)grow * DCAT;

    int bcol = tid >> 1;
    int bkb  = (tid & 1) * 16;

    float acc[4][4][4];
#pragma unroll
    for (int i = 0; i < 4; ++i)
#pragma unroll
        for (int j = 0; j < 4; ++j)
#pragma unroll
            for (int q = 0; q < 4; ++q) acc[i][j][q] = 0.0f;

    for (int k0 = 0; k0 < C; k0 += 32) {
        float av[16];
#pragma unroll
        for (int j = 0; j < 4; ++j) {
            float4 v = *(const float4*)(aptr + k0 + akb + j * 4);
            av[j * 4 + 0] = v.x; av[j * 4 + 1] = v.y;
            av[j * 4 + 2] = v.z; av[j * 4 + 3] = v.w;
        }
        uint4 wv_hi0 = *(const uint4*)(&Whi[bcol * C + k0 + bkb]);
        uint4 wv_hi1 = *(const uint4*)(&Whi[bcol * C + k0 + bkb + 8]);
        uint4 wv_lo0 = *(const uint4*)(&Wlo[bcol * C + k0 + bkb]);
        uint4 wv_lo1 = *(const uint4*)(&Wlo[bcol * C + k0 + bkb + 8]);

        unsigned ah[8], al[8];
#pragma unroll
        for (int j = 0; j < 8; ++j) {
            float v0 = av[2 * j], v1 = av[2 * j + 1];
            __nv_bfloat16 h0 = __float2bfloat16_rn(v0);
            __nv_bfloat16 h1 = __float2bfloat16_rn(v1);
            float l0 = v0 - __bfloat162float(h0);
            float l1 = v1 - __bfloat162float(h1);
            __nv_bfloat162 hp = __halves2bfloat162(h0, h1);
            __nv_bfloat162 lp = __halves2bfloat162(__float2bfloat16_rn(l0),
                                                   __float2bfloat16_rn(l1));
            ah[j] = *(unsigned*)&hp;
            al[j] = *(unsigned*)&lp;
        }

        __syncthreads();
        *(uint4*)&a_hi[arow][akb]     = make_uint4(ah[0], ah[1], ah[2], ah[3]);
        *(uint4*)&a_hi[arow][akb + 8] = make_uint4(ah[4], ah[5], ah[6], ah[7]);
        *(uint4*)&a_lo[arow][akb]     = make_uint4(al[0], al[1], al[2], al[3]);
        *(uint4*)&a_lo[arow][akb + 8] = make_uint4(al[4], al[5], al[6], al[7]);
        *(uint4*)&b_hi[bcol][bkb]     = wv_hi0;
        *(uint4*)&b_hi[bcol][bkb + 8] = wv_hi1;
        *(uint4*)&b_lo[bcol][bkb]     = wv_lo0;
        *(uint4*)&b_lo[bcol][bkb + 8] = wv_lo1;
        __syncthreads();

#pragma unroll
        for (int ks = 0; ks < 2; ++ks) {
            int kb = ks * 16 + (lane & 3) * 2;
            unsigned bh[4][2], bl[4][2];
#pragma unroll
            for (int ni = 0; ni < 4; ++ni) {
                int col = wn * 32 + ni * 8 + (lane >> 2);
                bh[ni][0] = *(unsigned*)&b_hi[col][kb];
                bh[ni][1] = *(unsigned*)&b_hi[col][kb + 8];
                bl[ni][0] = *(unsigned*)&b_lo[col][kb];
                bl[ni][1] = *(unsigned*)&b_lo[col][kb + 8];
            }
#pragma unroll
            for (int mi = 0; mi < 4; ++mi) {
                int r = wm * 64 + mi * 16 + (lane >> 2);
                unsigned AH[4], AL[4];
                AH[0] = *(unsigned*)&a_hi[r][kb];
                AH[1] = *(unsigned*)&a_hi[r + 8][kb];
                AH[2] = *(unsigned*)&a_hi[r][kb + 8];
                AH[3] = *(unsigned*)&a_hi[r + 8][kb + 8];
                AL[0] = *(unsigned*)&a_lo[r][kb];
                AL[1] = *(unsigned*)&a_lo[r + 8][kb];
                AL[2] = *(unsigned*)&a_lo[r][kb + 8];
                AL[3] = *(unsigned*)&a_lo[r + 8][kb + 8];
#pragma unroll
                for (int ni = 0; ni < 4; ++ni) {
                    mma_bf16(acc[mi][ni], AH, bh[ni]);
                    mma_bf16(acc[mi][ni], AL, bh[ni]);
                    mma_bf16(acc[mi][ni], AH, bl[ni]);
                }
            }
        }
    }

    // fp16-only epilogue (no fp32 mirror)
#pragma unroll
    for (int mi = 0; mi < 4; ++mi) {
        int r = row0 + wm * 64 + mi * 16 + (lane >> 2);
#pragma unroll
        for (int ni = 0; ni < 4; ++ni) {
            int col = wn * 32 + ni * 8 + (lane & 3) * 2;
            if (r < N_NODES)
                *(__half2*)(g_tmp16 + (size_t)r * C + col) =
                    __floats2half2_rn(acc[mi][ni][0], acc[mi][ni][1]);
            if (r + 8 < N_NODES)
                *(__half2*)(g_tmp16 + (size_t)(r + 8) * C + col) =
                    __floats2half2_rn(acc[mi][ni][2], acc[mi][ni][3]);
        }
    }
}

// ---------------------------------------------------------------------------
// Aggregation v3: one warp per node, 2 edges per iteration.
// Lanes 0-15 -> edge e, lanes 16-31 -> edge e+1; each lane loads uint4
// (8 fp16 channels). CSR prefetched 32-at-a-time, shuffle-broadcast.
// Final shuffle-combine; lanes 0-15 write 8 channels each.
// ---------------------------------------------------------------------------
__global__ void k_aggr(const float* __restrict__ b, float* __restrict__ out) {
    int warp = (blockIdx.x * blockDim.x + threadIdx.x) >> 5;
    int lane = threadIdx.x & 31;
    if (warp >= N_NODES) return;

    int rs = g_rowstart[warp];
    int re = g_rowstart[warp + 1];
    int half  = lane >> 4;          // 0: even edges, 1: odd edges
    int sub   = lane & 15;          // channel group 0..15
    int choff = sub * 8;            // 8 halves = 16 B

    float acc[8];
#pragma unroll
    for (int j = 0; j < 8; ++j) acc[j] = 0.0f;

    for (int base = rs; base < re; base += 32) {
        int2 myc = (base + lane < re) ? g_csr[base + lane] : make_int2(0, 0);
        int nIter = re - base; if (nIter > 32) nIter = 32;
#pragma unroll 4
        for (int i = 0; i < nIter; i += 2) {
            int eidx = i + half;
            int src  = __shfl_sync(0xffffffffu, myc.x, eidx);
            int wbits = __shfl_sync(0xffffffffu, myc.y, eidx);
            float w = (eidx < nIter) ? __int_as_float(wbits) : 0.0f;
            uint4 u = *(const uint4*)(g_tmp16 + (size_t)src * C + choff);
            const __half2* hp = (const __half2*)&u;
#pragma unroll
            for (int j = 0; j < 4; ++j) {
                float2 f = __half22float2(hp[j]);
                acc[2 * j]     = fmaf(f.x, w, acc[2 * j]);
                acc[2 * j + 1] = fmaf(f.y, w, acc[2 * j + 1]);
            }
        }
    }

    // combine odd-edge half into even-edge half
#pragma unroll
    for (int j = 0; j < 8; ++j)
        acc[j] += __shfl_down_sync(0xffffffffu, acc[j], 16);

    if (half == 0) {
        float di = g_dis[warp];
        float d2 = di * di;
        uint4 su = *(const uint4*)(g_tmp16 + (size_t)warp * C + choff);
        const __half2* sp = (const __half2*)&su;
        float4 b0 = *(const float4*)(b + choff);
        float4 b1 = *(const float4*)(b + choff + 4);
        float sv[8];
#pragma unroll
        for (int j = 0; j < 4; ++j) {
            float2 f = __half22float2(sp[j]);
            sv[2 * j] = f.x; sv[2 * j + 1] = f.y;
        }
        float o[8];
        o[0] = fmaf(acc[0], di, fmaf(sv[0], d2, b0.x));
        o[1] = fmaf(acc[1], di, fmaf(sv[1], d2, b0.y));
        o[2] = fmaf(acc[2], di, fmaf(sv[2], d2, b0.z));
        o[3] = fmaf(acc[3], di, fmaf(sv[3], d2, b0.w));
        o[4] = fmaf(acc[4], di, fmaf(sv[4], d2, b1.x));
        o[5] = fmaf(acc[5], di, fmaf(sv[5], d2, b1.y));
        o[6] = fmaf(acc[6], di, fmaf(sv[6], d2, b1.z));
        o[7] = fmaf(acc[7], di, fmaf(sv[7], d2, b1.w));
        float* op = out + (size_t)warp * DCAT + choff;
        *(float4*)op       = make_float4(o[0], o[1], o[2], o[3]);
        *(float4*)(op + 4) = make_float4(o[4], o[5], o[6], o[7]);
    }
}

// ---------------------------------------------------------------------------
// Final linear: labels[N,16] = h[N,512] @ W_lin[512,16] + b_lin
// ---------------------------------------------------------------------------
__global__ void k_lin(const float* __restrict__ h, const float* __restrict__ Wl,
                      const float* __restrict__ bl, float* __restrict__ out) {
    __shared__ float ws[DCAT * 17];
    __shared__ float bs[NCLS];
    for (int idx = threadIdx.x; idx < DCAT * NCLS; idx += blockDim.x) {
        int c = idx >> 4;
        int k = idx & 15;
        ws[c * 17 + k] = Wl[idx];
    }
    if (threadIdx.x < NCLS) bs[threadIdx.x] = bl[threadIdx.x];
    __syncthreads();

    int warp = threadIdx.x >> 5;
    int lane = threadIdx.x & 31;
    int warpsPerGrid = (blockDim.x >> 5) * gridDim.x;
    for (int node = blockIdx.x * (blockDim.x >> 5) + warp; node < N_NODES;
         node += warpsPerGrid) {
        float acc[NCLS];
#pragma unroll
        for (int k = 0; k < NCLS; ++k) acc[k] = 0.0f;
        const float* hr = h + (size_t)node * DCAT;
#pragma unroll
        for (int j = 0; j < 4; ++j) {
            int cidx = j * 128 + lane * 4;
            float4 hv = *(const float4*)(hr + cidx);
            const float* w0 = &ws[(cidx + 0) * 17];
            const float* w1 = &ws[(cidx + 1) * 17];
            const float* w2 = &ws[(cidx + 2) * 17];
            const float* w3 = &ws[(cidx + 3) * 17];
#pragma unroll
            for (int k = 0; k < NCLS; ++k)
                acc[k] = fmaf(hv.x, w0[k], fmaf(hv.y, w1[k],
                         fmaf(hv.z, w2[k], fmaf(hv.w, w3[k], acc[k]))));
        }
#pragma unroll
        for (int off = 16; off > 0; off >>= 1) {
#pragma unroll
            for (int k = 0; k < NCLS; ++k)
                acc[k] += __shfl_xor_sync(0xffffffffu, acc[k], off);
        }
        if (lane == 0) {
            float* op = out + (size_t)node * NCLS;
#pragma unroll
            for (int k = 0; k < NCLS; ++k) op[k] = acc[k] + bs[k];
        }
    }
}

// ---------------------------------------------------------------------------
extern "C" void kernel_launch(void* const* d_in, const int* in_sizes, int n_in,
                              void* d_out, int out_size) {
    const float* x     = (const float*)d_in[0];
    const int*   ei    = (const int*)d_in[1];      // int32 (JAX x64 off)
    const float* W1    = (const float*)d_in[2];
    const float* b1    = (const float*)d_in[3];
    const float* W2    = (const float*)d_in[4];
    const float* b2    = (const float*)d_in[5];
    const float* W3    = (const float*)d_in[6];
    const float* b3    = (const float*)d_in[7];
    const float* W_lin = (const float*)d_in[8];
    const float* b_lin = (const float*)d_in[9];
    const float* bias[3] = {b1, b2, b3};

    float* labels = (float*)d_out;                      // [N, 16]
    float* h      = labels + (size_t)N_NODES * NCLS;    // [N, 512]

    const int TB = 256;
    k_init <<<(N_NODES * 32 + TB - 1) / TB, TB>>>(x, h);
    k_wconv<<<(3 * C * C + TB - 1) / TB, TB>>>(W1, W2, W3);
    k_deg  <<<(N_EDGES + TB - 1) / TB, TB>>>(ei);
    k_gemm_tc<<<(N_NODES + 127) / 128, 256>>>(h, 0);   // layer 1 GEMM
    k_scanA<<<NB, SB>>>();
    k_scanB<<<1, 128>>>();
    k_scanC<<<(N_NODES + TB - 1) / TB, TB>>>();
    k_fill <<<(N_EDGES + TB - 1) / TB, TB>>>(ei);

    k_aggr<<<(N_NODES * 32 + TB - 1) / TB, TB>>>(bias[0], h + 1 * C);
    for (int l = 1; l < 3; ++l) {
        k_gemm_tc<<<(N_NODES + 127) / 128, 256>>>(h + l * C, l);
        k_aggr<<<(N_NODES * 32 + TB - 1) / TB, TB>>>(bias[l], h + (l + 1) * C);
    }

    k_lin<<<2048, 256>>>(h, W_lin, b_lin, labels);
}